// round 15
// baseline (speedup 1.0000x reference)
#include <cuda_runtime.h>
#include <cuda_bf16.h>
#include <math.h>
#include <stdint.h>

// ---------------- problem constants ----------------
#define B4    4
#define C0IN  64
#define C0OUT 192
#define C1OUT 576
#define NPIX  (96*96)          // 9216
#define PDIM  98
#define PPIX  (98*98)          // 9604
#define HP    48               // pooled size

// ---------------- scratch (device globals; no allocation allowed) ----------
__device__ float g_xp [B4*C0IN*PPIX];     // padded x, [B][4][98][98][8w] bf16x2
__device__ float g_y  [B4*C0OUT*NPIX];    // after conv0+bn+relu (fp32)
__device__ float g_tp [B4*C0OUT*PPIX];    // padded concat, [B][12][98][98][8w] bf16x2
__device__ float g_qkb[B4*384*NPIX/2];    // q/k channels as bf16 [B][384][9216]
__device__ float g_vb [B4*192*NPIX/2];    // v channels as bf16 [B][192][9216]
__device__ float g_att[B4*192*192];       // attention logits / probs
__device__ float g_o  [B4*C0OUT*NPIX];    // attn @ v
__device__ float g_sq [B4*384];           // sum of squares q (0:192) / k (192:384)
__device__ float g_w0t[C0OUT*C0IN*9];     // repacked bf16 weights conv0 (oversized)
__device__ float g_w1t[C1OUT*C0OUT*9];    // repacked bf16 weights conv1 (oversized)

// ---------------- helpers ----------------
__device__ __forceinline__ uint32_t pack_bf16(float lo, float hi) {
    __nv_bfloat162 v = __floats2bfloat162_rn(lo, hi);
    return *(uint32_t*)&v;
}
__device__ __forceinline__ void mma_bf16(float c[4],
    uint32_t a0, uint32_t a1, uint32_t a2, uint32_t a3,
    uint32_t b0, uint32_t b1)
{
    asm volatile(
        "mma.sync.aligned.m16n8k16.row.col.f32.bf16.bf16.f32 "
        "{%0,%1,%2,%3}, {%4,%5,%6,%7}, {%8,%9}, {%0,%1,%2,%3};"
        : "+f"(c[0]), "+f"(c[1]), "+f"(c[2]), "+f"(c[3])
        : "r"(a0), "r"(a1), "r"(a2), "r"(a3), "r"(b0), "r"(b1));
}
__device__ __forceinline__ void cp16(void* s, const void* g) {
    uint32_t sa = (uint32_t)__cvta_generic_to_shared(s);
    asm volatile("cp.async.cg.shared.global [%0], [%1], 16;" :: "r"(sa), "l"(g));
}
// conv word layout (16 ch -> 8 uint32 words): word j holds channel pair pc where
//   j = (pc & 3)*2 + (pc >> 2)  /  pc = (j >> 1) + ((j & 1) << 2)

// =====================================================================
// Weight repack: w[CO,CI,3,3] fp32 -> bf16 words
// =====================================================================
__global__ __launch_bounds__(256) void repack_w_kernel(
    const float* __restrict__ w, float* __restrict__ outf, int CI, int CO)
{
    uint32_t* out = (uint32_t*)outf;
    const int total = CO * (CI >> 4) * 9 * 8;
    for (int d = blockIdx.x*256 + threadIdx.x; d < total; d += gridDim.x*256) {
        int j   = d & 7;
        int rem = d >> 3;
        int co  = rem % CO;  rem /= CO;
        int rs  = rem % 9;
        int chunk = rem / 9;
        int pc = (j >> 1) + ((j & 1) << 2);
        int c_lo = chunk*16 + pc*2;
        out[d] = pack_bf16(w[((size_t)co*CI + c_lo    )*9 + rs],
                           w[((size_t)co*CI + c_lo + 1)*9 + rs]);
    }
}

// =====================================================================
// Implicit-GEMM 3x3 conv + bias + BN + ReLU, bf16 m16n8k16 MMA.
// Tile: M=64 out-channels x 2 output rows (192 px). 8 warps =
// 2(M-half) x 2(row) x 2(ni-half). 3 CTAs/SM target.
// =====================================================================
#define SW_BYTES 18432   // 9*64*8w*4
#define SX_BYTES 12544   // 4*98*8w*4
#define CONV_SMEM (2*SW_BYTES + 2*SX_BYTES)   // 61952

__global__ __launch_bounds__(256, 3) void conv3x3_mma(
    const float* __restrict__ in,   // bf16 words, [B][CI/16][98][98][8w]
    const float* __restrict__ wt,   // repacked bf16 weights
    const float* __restrict__ bias, const float* __restrict__ gam,
    const float* __restrict__ bet,  const float* __restrict__ mu,
    const float* __restrict__ var,  float* __restrict__ out, // fp32 [B,CO,96,96]
    int do_qk, int CI, int CO)
{
    extern __shared__ uint8_t dynsm[];

    const int tid  = threadIdx.x;
    const int warp = tid >> 5;
    const int lane = tid & 31;
    const int g    = lane >> 2;
    const int tig  = lane & 3;
    const int wn   = warp & 1;            // row 0..1
    const int wm   = (warp >> 1) & 1;     // M half 0..1
    const int wh   = warp >> 2;           // ni half 0..1

    const int y0o = blockIdx.x * 2;
    const int co0 = blockIdx.y * 64;
    const int b   = blockIdx.z;
    const int nchunks = CI >> 4;

    const uint4* w4 = (const uint4*)wt;

    float acc[2][6][4];
#pragma unroll
    for (int mi = 0; mi < 2; mi++)
#pragma unroll
        for (int ni = 0; ni < 6; ni++)
#pragma unroll
            for (int q = 0; q < 4; q++) acc[mi][ni][q] = 0.f;

    auto load_chunk = [&](int chunk, int stg) {
        uint4* wdst = (uint4*)(dynsm + stg*SW_BYTES);
        const uint4* wsrc = w4 + ((size_t)chunk*9*CO + co0)*2;
        for (int l = tid; l < 1152; l += 256) {
            int rs = l >> 7, t = l & 127;
            cp16(wdst + l, wsrc + (size_t)rs*CO*2 + t);
        }
        uint4* xdst = (uint4*)(dynsm + 2*SW_BYTES + stg*SX_BYTES);
        const uint4* xsrc = (const uint4*)in +
            (((size_t)(b*nchunks + chunk))*PPIX + (size_t)y0o*98)*2;
        for (int l = tid; l < 784; l += 256)
            cp16(xdst + l, xsrc + l);
    };

    load_chunk(0, 0);
    asm volatile("cp.async.commit_group;" ::: "memory");

    for (int chunk = 0; chunk < nchunks; chunk++) {
        const int st = chunk & 1;
        const bool more = (chunk + 1 < nchunks);
        if (more) {
            load_chunk(chunk + 1, st ^ 1);
            asm volatile("cp.async.commit_group;" ::: "memory");
            asm volatile("cp.async.wait_group 1;" ::: "memory");
        } else {
            asm volatile("cp.async.wait_group 0;" ::: "memory");
        }
        __syncthreads();

        const uint32_t (*W8)[64][8] = (const uint32_t (*)[64][8])(dynsm + st*SW_BYTES);
        const uint32_t (*X8)[98][8] = (const uint32_t (*)[98][8])(dynsm + 2*SW_BYTES + st*SX_BYTES);

#pragma unroll
        for (int r = 0; r < 3; r++) {
#pragma unroll
            for (int s = 0; s < 3; s++) {
                const int rs = r*3 + s;
                const int base0 = wm*32 + g;
                uint2 va00 = *(const uint2*)&W8[rs][base0     ][tig*2];
                uint2 va01 = *(const uint2*)&W8[rs][base0 +  8][tig*2];
                uint2 va10 = *(const uint2*)&W8[rs][base0 + 16][tig*2];
                uint2 va11 = *(const uint2*)&W8[rs][base0 + 24][tig*2];
                const int prow = wn + r;
                const int colb = wh*48 + g + s;
#pragma unroll
                for (int ni = 0; ni < 6; ni++) {
                    uint2 vb = *(const uint2*)&X8[prow][colb + ni*8][tig*2];
                    mma_bf16(acc[0][ni], va00.x, va01.x, va00.y, va01.y, vb.x, vb.y);
                    mma_bf16(acc[1][ni], va10.x, va11.x, va10.y, va11.y, vb.x, vb.y);
                }
            }
        }
        __syncthreads();
    }

    // epilogue
    const int orow = y0o + wn;
    const int x0 = wh*48 + tig*2;
#pragma unroll
    for (int mi = 0; mi < 2; mi++) {
        int c_lo = co0 + wm*32 + mi*16 + g;
        int c_hi = c_lo + 8;
        float s_lo  = gam[c_lo] * rsqrtf(var[c_lo] + 1e-5f);
        float sh_lo = (bias[c_lo] - mu[c_lo]) * s_lo + bet[c_lo];
        float s_hi  = gam[c_hi] * rsqrtf(var[c_hi] + 1e-5f);
        float sh_hi = (bias[c_hi] - mu[c_hi]) * s_hi + bet[c_hi];

        if (do_qk && c_lo < 384) {
            uint32_t* qlo = (uint32_t*)g_qkb + (((size_t)(b*384 + c_lo))*NPIX + orow*96)/2;
            uint32_t* qhi = (uint32_t*)g_qkb + (((size_t)(b*384 + c_hi))*NPIX + orow*96)/2;
            float sql = 0.f, sqh = 0.f;
#pragma unroll
            for (int ni = 0; ni < 6; ni++) {
                int x = x0 + ni*8;
                float2 v0 = make_float2(fmaxf(acc[mi][ni][0]*s_lo + sh_lo, 0.f),
                                        fmaxf(acc[mi][ni][1]*s_lo + sh_lo, 0.f));
                float2 v1 = make_float2(fmaxf(acc[mi][ni][2]*s_hi + sh_hi, 0.f),
                                        fmaxf(acc[mi][ni][3]*s_hi + sh_hi, 0.f));
                qlo[x/2] = pack_bf16(v0.x, v0.y);
                qhi[x/2] = pack_bf16(v1.x, v1.y);
                sql += v0.x*v0.x + v0.y*v0.y;
                sqh += v1.x*v1.x + v1.y*v1.y;
            }
            sql += __shfl_xor_sync(0xFFFFFFFFu, sql, 1);
            sql += __shfl_xor_sync(0xFFFFFFFFu, sql, 2);
            sqh += __shfl_xor_sync(0xFFFFFFFFu, sqh, 1);
            sqh += __shfl_xor_sync(0xFFFFFFFFu, sqh, 2);
            if (tig == 0) {
                atomicAdd(&g_sq[b*384 + c_lo], sql);
                atomicAdd(&g_sq[b*384 + c_hi], sqh);
            }
        } else if (do_qk) {
            uint32_t* vlo = (uint32_t*)g_vb + (((size_t)(b*192 + c_lo - 384))*NPIX + orow*96)/2;
            uint32_t* vhi = (uint32_t*)g_vb + (((size_t)(b*192 + c_hi - 384))*NPIX + orow*96)/2;
#pragma unroll
            for (int ni = 0; ni < 6; ni++) {
                int x = x0 + ni*8;
                vlo[x/2] = pack_bf16(fmaxf(acc[mi][ni][0]*s_lo + sh_lo, 0.f),
                                     fmaxf(acc[mi][ni][1]*s_lo + sh_lo, 0.f));
                vhi[x/2] = pack_bf16(fmaxf(acc[mi][ni][2]*s_hi + sh_hi, 0.f),
                                     fmaxf(acc[mi][ni][3]*s_hi + sh_hi, 0.f));
            }
        } else {
            float* plo = out + (size_t)(b*CO + c_lo)*NPIX + orow*96;
            float* phi = out + (size_t)(b*CO + c_hi)*NPIX + orow*96;
#pragma unroll
            for (int ni = 0; ni < 6; ni++) {
                int x = x0 + ni*8;
                *(float2*)(plo + x) = make_float2(fmaxf(acc[mi][ni][0]*s_lo + sh_lo, 0.f),
                                                  fmaxf(acc[mi][ni][1]*s_lo + sh_lo, 0.f));
                *(float2*)(phi + x) = make_float2(fmaxf(acc[mi][ni][2]*s_hi + sh_hi, 0.f),
                                                  fmaxf(acc[mi][ni][3]*s_hi + sh_hi, 0.f));
            }
        }
    }
}

// =====================================================================
// Pad x -> g_xp [B][4][98][98][8w] bf16 words. grid = B4*4*7 row-bands.
// =====================================================================
__global__ __launch_bounds__(256) void pad_x_kernel(const float* __restrict__ x)
{
    const int z = blockIdx.x;
    const int band  = z % 7;
    const int chunk = (z / 7) & 3;
    const int b     = z / 28;
    uint32_t* dp = (uint32_t*)g_xp + ((size_t)(b*4 + chunk))*PPIX*8;
    const float* sp = x + ((size_t)b*C0IN + chunk*16)*NPIX;
    for (int i = threadIdx.x; i < 14*98*8; i += 256) {
        int j = i & 7;
        int p = i >> 3;
        int lrow = p / 98, col = p % 98;
        int row = band*14 + lrow;
        int pc = (j >> 1) + ((j & 1) << 2);
        int c_lo = pc*2;
        float vlo = 0.f, vhi = 0.f;
        if (row >= 1 && row <= 96 && col >= 1 && col <= 96) {
            vlo = sp[(size_t)(c_lo    )*NPIX + (row-1)*96 + (col-1)];
            vhi = sp[(size_t)(c_lo + 1)*NPIX + (row-1)*96 + (col-1)];
        }
        dp[((size_t)row*98 + col)*8 + j] = pack_bf16(vlo, vhi);
    }
}

// =====================================================================
// Branch construction into g_tp [B][12][98][98][8w] bf16 words.
// =====================================================================
#define POOLPAD (HP*HP + 1)
#define BUILD_SMEM (8*POOLPAD*4)    // 73760 B

__global__ __launch_bounds__(1024) void build_t_kernel()
{
    extern __shared__ float pool[];
    const int z = blockIdx.x;         // 0..95
    const int half  = z & 1;
    const int chunk = (z >> 1) % 12;
    const int b     = z / 24;
    const int tid = threadIdx.x;
    uint32_t* dp = (uint32_t*)g_tp + ((size_t)(b*12 + chunk))*PPIX*8;
    const float* yb = g_y + ((size_t)b*192)*NPIX;
    const int c0 = chunk*16 + half*8;

    if (chunk >= 4 && chunk < 8) {        // copy branch
        for (int i = tid; i < PPIX*4; i += 1024) {
            int pl = i & 3;
            int p  = i >> 2;
            int row = p / 98, col = p % 98;
            float vlo = 0.f, vhi = 0.f;
            if (row >= 1 && row <= 96 && col >= 1 && col <= 96) {
                const float* yp = yb + (size_t)(c0 + pl*2)*NPIX + (row-1)*96 + (col-1);
                vlo = yp[0];
                vhi = yp[NPIX];
            }
            dp[(size_t)p*8 + pl*2 + half] = pack_bf16(vlo, vhi);
        }
        return;
    }

    const bool is_max = (chunk < 4);
    for (int i = tid; i < 8*HP*HP; i += 1024) {
        int lc = i / (HP*HP);
        int idx = i % (HP*HP);
        int p = idx / HP, q = idx % HP;
        const float* yp = yb + (size_t)(c0 + lc)*NPIX;
        float a  = yp[(2*p)  *96 + 2*q    ];
        float bb = yp[(2*p)  *96 + 2*q + 1];
        float cc = yp[(2*p+1)*96 + 2*q    ];
        float dd = yp[(2*p+1)*96 + 2*q + 1];
        pool[lc*POOLPAD + idx] = is_max ? fmaxf(fmaxf(a,bb), fmaxf(cc,dd))
                                        : 0.25f*(a + bb + cc + dd);
    }
    __syncthreads();

    for (int i = tid; i < PPIX*4; i += 1024) {
        int pl = i & 3;
        int p  = i >> 2;
        int row = p / 98, col = p % 98;
        uint32_t word = 0;
        if (row >= 1 && row <= 96 && col >= 1 && col <= 96) {
            int h = row - 1, w = col - 1;
            float chf = fminf(fmaxf(0.5f*h - 0.25f, 0.f), 47.f);
            float cwf = fminf(fmaxf(0.5f*w - 0.25f, 0.f), 47.f);
            int hlo = (int)chf; int hhi = min(hlo + 1, 47); float hf = chf - hlo;
            int wlo = (int)cwf; int whi = min(wlo + 1, 47); float wf = cwf - wlo;
            const float* p0 = pool + (pl*2    )*POOLPAD;
            const float* p1 = pool + (pl*2 + 1)*POOLPAD;
            float t0 = p0[hlo*HP + wlo]*(1.f - wf) + p0[hlo*HP + whi]*wf;
            float b0 = p0[hhi*HP + wlo]*(1.f - wf) + p0[hhi*HP + whi]*wf;
            float t1 = p1[hlo*HP + wlo]*(1.f - wf) + p1[hlo*HP + whi]*wf;
            float b1 = p1[hhi*HP + wlo]*(1.f - wf) + p1[hhi*HP + whi]*wf;
            word = pack_bf16(t0*(1.f - hf) + b0*hf, t1*(1.f - hf) + b1*hf);
        }
        dp[(size_t)p*8 + pl*2 + half] = word;
    }
}

// =====================================================================
// QK^T via bf16 MMA on bf16 q/k buffer, cp.async double-buffered (R12).
// =====================================================================
#define QK_STAGE 17408   // Q half + K half = 8704 each

__global__ __launch_bounds__(256) void qk_mma_kernel(const float* __restrict__ temp)
{
    __shared__ __align__(16) uint8_t smraw[2*QK_STAGE];   // 34816 B
    __shared__ float sQi[32], sKi[32];
    float (*sP)[32][33] = (float(*)[32][33])smraw;        // alias after mainloop

    const int b = blockIdx.z;
    const int i0 = blockIdx.y * 32, j0 = blockIdx.x * 32;
    const int tid  = threadIdx.x;
    const int warp = tid >> 5;
    const int lane = tid & 31;
    const int g    = lane >> 2;
    const int tig  = lane & 3;

    const uint16_t* qkb = (const uint16_t*)g_qkb;
    const uint16_t* Qb = qkb + ((size_t)(b*384) + i0)*NPIX;
    const uint16_t* Kb = qkb + ((size_t)(b*384) + 192 + j0)*NPIX;

    auto load = [&](int kt, int stg) {
        uint8_t* qdst = smraw + stg*QK_STAGE;
        uint8_t* kdst = qdst + 8704;
        for (int l = tid; l < 512; l += 256) {
            int row = l >> 4, seg = l & 15;
            cp16(qdst + row*272 + seg*16, Qb + (size_t)row*NPIX + kt + seg*8);
            cp16(kdst + row*272 + seg*16, Kb + (size_t)row*NPIX + kt + seg*8);
        }
    };

    float acc[2][4][4];
#pragma unroll
    for (int mt = 0; mt < 2; mt++)
#pragma unroll
        for (int nt = 0; nt < 4; nt++)
#pragma unroll
            for (int q = 0; q < 4; q++) acc[mt][nt][q] = 0.f;

    load(0, 0);
    asm volatile("cp.async.commit_group;" ::: "memory");

    const int kw0 = warp * 8;
    for (int c = 0; c < 72; c++) {
        const int st = c & 1;
        if (c + 1 < 72) {
            load((c + 1)*128, st ^ 1);
            asm volatile("cp.async.commit_group;" ::: "memory");
            asm volatile("cp.async.wait_group 1;" ::: "memory");
        } else {
            asm volatile("cp.async.wait_group 0;" ::: "memory");
        }
        __syncthreads();

        const uint32_t (*Q8)[68] = (const uint32_t (*)[68])(smraw + st*QK_STAGE);
        const uint32_t (*K8)[68] = (const uint32_t (*)[68])(smraw + st*QK_STAGE + 8704);

        uint32_t a[2][4];
#pragma unroll
        for (int mt = 0; mt < 2; mt++) {
            int r0 = mt*16 + g;
            a[mt][0] = Q8[r0    ][kw0 + tig];
            a[mt][1] = Q8[r0 + 8][kw0 + tig];
            a[mt][2] = Q8[r0    ][kw0 + 4 + tig];
            a[mt][3] = Q8[r0 + 8][kw0 + 4 + tig];
        }
#pragma unroll
        for (int nt = 0; nt < 4; nt++) {
            int jr = nt*8 + g;
            uint32_t b0 = K8[jr][kw0 + tig];
            uint32_t b1 = K8[jr][kw0 + 4 + tig];
            mma_bf16(acc[0][nt], a[0][0], a[0][1], a[0][2], a[0][3], b0, b1);
            mma_bf16(acc[1][nt], a[1][0], a[1][1], a[1][2], a[1][3], b0, b1);
        }
        __syncthreads();
    }

    if (tid < 32)
        sQi[tid] = 1.f / fmaxf(sqrtf(g_sq[b*384 + i0 + tid]), 1e-12f);
    else if (tid < 64)
        sKi[tid-32] = 1.f / fmaxf(sqrtf(g_sq[b*384 + 192 + j0 + tid - 32]), 1e-12f);
#pragma unroll
    for (int mt = 0; mt < 2; mt++)
#pragma unroll
        for (int nt = 0; nt < 4; nt++) {
            int r = mt*16 + g, cix = nt*8 + tig*2;
            sP[warp][r    ][cix    ] = acc[mt][nt][0];
            sP[warp][r    ][cix + 1] = acc[mt][nt][1];
            sP[warp][r + 8][cix    ] = acc[mt][nt][2];
            sP[warp][r + 8][cix + 1] = acc[mt][nt][3];
        }
    __syncthreads();

    float tmp = temp[0];
    for (int o = tid; o < 1024; o += 256) {
        int row = o >> 5, col = o & 31;
        float s = 0.f;
#pragma unroll
        for (int w = 0; w < 8; w++) s += sP[w][row][col];
        g_att[(size_t)(b*192 + i0 + row)*192 + j0 + col] =
            s * sQi[row] * tmp * sKi[col];
    }
}

// =====================================================================
// Softmax over last dim (192).
// =====================================================================
__global__ __launch_bounds__(256) void softmax_kernel()
{
    const int row = blockIdx.x;          // 0..767
    float* p = g_att + (size_t)row * 192;
    const int t = threadIdx.x;
    __shared__ float sm[256];
    float v = (t < 192) ? p[t] : -3.0e38f;
    sm[t] = v; __syncthreads();
    for (int s = 128; s > 0; s >>= 1) {
        if (t < s) sm[t] = fmaxf(sm[t], sm[t+s]);
        __syncthreads();
    }
    float mx = sm[0]; __syncthreads();
    float e = (t < 192) ? expf(v - mx) : 0.f;
    sm[t] = e; __syncthreads();
    for (int s = 128; s > 0; s >>= 1) {
        if (t < s) sm[t] += sm[t+s];
        __syncthreads();
    }
    float inv = 1.f / sm[0];
    if (t < 192) p[t] = e * inv;
}

// =====================================================================
// O = A @ V via bf16 MMA (R12 form). CTA tile 32(i) x 128(n).
// =====================================================================
__global__ __launch_bounds__(256) void av_mma_kernel()
{
    __shared__ uint32_t As[32][100];     // 96 words + pad   12.8 KB
    __shared__ uint32_t Vs[128][20];     // 16 words + pad   10.2 KB

    const int b  = blockIdx.z;
    const int i0 = blockIdx.y * 32;
    const int n0 = blockIdx.x * 128;
    const int tid  = threadIdx.x;
    const int warp = tid >> 5;
    const int lane = tid & 31;
    const int g    = lane >> 2;
    const int tig  = lane & 3;

    const float* A = g_att + (size_t)b * 192 * 192;
    const uint32_t* vb = (const uint32_t*)g_vb + (size_t)b * 192 * (NPIX/2);

#pragma unroll
    for (int jj = 0; jj < 12; jj++) {
        int l = jj*256 + tid;
        int r = l / 96, w = l % 96;
        float2 a2 = *(const float2*)&A[(size_t)(i0 + r)*192 + 2*w];
        As[r][w] = pack_bf16(a2.x, a2.y);
    }

    float acc[2][2][4];
#pragma unroll
    for (int mt = 0; mt < 2; mt++)
#pragma unroll
        for (int nt = 0; nt < 2; nt++)
#pragma unroll
            for (int q = 0; q < 4; q++) acc[mt][nt][q] = 0.f;

    for (int kt = 0; kt < 192; kt += 32) {
        __syncthreads();
        for (int l = tid; l < 1024; l += 256) {
            int pp = l & 63;
            int w  = l >> 6;
            uint32_t u0 = vb[(size_t)(kt + 2*w    )*(NPIX/2) + (n0 >> 1) + pp];
            uint32_t u1 = vb[(size_t)(kt + 2*w + 1)*(NPIX/2) + (n0 >> 1) + pp];
            Vs[2*pp    ][w] = __byte_perm(u0, u1, 0x5410);
            Vs[2*pp + 1][w] = __byte_perm(u0, u1, 0x7632);
        }
        __syncthreads();

        const int wt0 = kt >> 1;
#pragma unroll
        for (int ks = 0; ks < 2; ks++) {
            const int kw = wt0 + ks*8;
            uint32_t a[2][4];
#pragma unroll
            for (int mt = 0; mt < 2; mt++) {
                int r0 = mt*16 + g;
                a[mt][0] = As[r0    ][kw + tig];
                a[mt][1] = As[r0 + 8][kw + tig];
                a[mt][2] = As[r0    ][kw + 4 + tig];
                a[mt][3] = As[r0 + 8][kw + 4 + tig];
            }
#pragma unroll
            for (int nt = 0; nt < 2; nt++) {
                int nr = warp*16 + nt*8 + g;
                uint32_t b0 = Vs[nr][ks*8 + tig];
                uint32_t b1 = Vs[nr][ks*8 + 4 + tig];
                mma_bf16(acc[0][nt], a[0][0], a[0][1], a[0][2], a[0][3], b0, b1);
                mma_bf16(acc[1][nt], a[1][0], a[1][1], a[1][2], a[1][3], b0, b1);
            }
        }
    }

#pragma unroll
    for (int mt = 0; mt < 2; mt++) {
        int r = i0 + mt*16 + g;
#pragma unroll
        for (int nt = 0; nt < 2; nt++) {
            int nc = n0 + warp*16 + nt*8 + tig*2;
            *(float2*)&g_o[((size_t)(b*192) + r    )*NPIX + nc] =
                make_float2(acc[mt][nt][0], acc[mt][nt][1]);
            *(float2*)&g_o[((size_t)(b*192) + r + 8)*NPIX + nc] =
                make_float2(acc[mt][nt][2], acc[mt][nt][3]);
        }
    }
}

// =====================================================================
// Depthwise 3x3 conv (pad 1) + bias on g_o -> d_out.
// =====================================================================
__global__ __launch_bounds__(256) void dwconv_kernel(
    const float* __restrict__ w2, const float* __restrict__ b2,
    float* __restrict__ out)
{
    __shared__ float sIn[34][34];
    const int tx = threadIdx.x, ty = threadIdx.y;
    const int tid = ty*16 + tx;
    const int z = blockIdx.z;            // 0..767
    const int b = z / 192, c = z % 192;
    const int y0 = blockIdx.y*32, x0 = blockIdx.x*32;
    const float* ip = g_o + (size_t)(b*192 + c) * NPIX;

    for (int l = tid; l < 34*34; l += 256) {
        int i = l / 34, j = l % 34;
        int gy = y0 - 1 + i, gx = x0 - 1 + j;
        float v = 0.f;
        if ((unsigned)gy < 96u && (unsigned)gx < 96u) v = ip[gy*96 + gx];
        ((float*)sIn)[l] = v;
    }
    __syncthreads();

    float wv[9];
#pragma unroll
    for (int k = 0; k < 9; k++) wv[k] = w2[c*9 + k];
    float bb = b2[c];

    float iv[4][4];
#pragma unroll
    for (int r = 0; r < 4; r++)
#pragma unroll
        for (int cc = 0; cc < 4; cc++) iv[r][cc] = sIn[2*ty + r][2*tx + cc];

    float a00 = bb, a01 = bb, a10 = bb, a11 = bb;
#pragma unroll
    for (int ky = 0; ky < 3; ky++)
#pragma unroll
        for (int kx = 0; kx < 3; kx++) {
            float wk = wv[ky*3 + kx];
            a00 += iv[ky  ][kx  ]*wk;
            a01 += iv[ky  ][kx+1]*wk;
            a10 += iv[ky+1][kx  ]*wk;
            a11 += iv[ky+1][kx+1]*wk;
        }
    const int oy = y0 + 2*ty, ox = x0 + 2*tx;
    float* op = out + (size_t)(b*192 + c)*NPIX + oy*96 + ox;
    op[0] = a00; op[1] = a01; op[96] = a10; op[97] = a11;
}

// =====================================================================
// Launcher
// =====================================================================
extern "C" void kernel_launch(void* const* d_in, const int* in_sizes, int n_in,
                              void* d_out, int out_size)
{
    const float* x    = (const float*)d_in[0];
    const float* w0   = (const float*)d_in[1];
    const float* b0   = (const float*)d_in[2];
    const float* g0   = (const float*)d_in[3];
    const float* be0  = (const float*)d_in[4];
    const float* m0   = (const float*)d_in[5];
    const float* v0   = (const float*)d_in[6];
    const float* w1   = (const float*)d_in[7];
    const float* b1   = (const float*)d_in[8];
    const float* g1   = (const float*)d_in[9];
    const float* be1  = (const float*)d_in[10];
    const float* m1   = (const float*)d_in[11];
    const float* v1   = (const float*)d_in[12];
    const float* temp = (const float*)d_in[13];
    const float* w2   = (const float*)d_in[14];
    const float* b2   = (const float*)d_in[15];
    float* out = (float*)d_out;

    float *pxp, *py, *ptp, *pw0t, *pw1t, *psq;
    cudaGetSymbolAddress((void**)&pxp,  g_xp);
    cudaGetSymbolAddress((void**)&py,   g_y);
    cudaGetSymbolAddress((void**)&ptp,  g_tp);
    cudaGetSymbolAddress((void**)&pw0t, g_w0t);
    cudaGetSymbolAddress((void**)&pw1t, g_w1t);
    cudaGetSymbolAddress((void**)&psq,  g_sq);

    cudaFuncSetAttribute(conv3x3_mma,
        cudaFuncAttributeMaxDynamicSharedMemorySize, CONV_SMEM);
    cudaFuncSetAttribute(build_t_kernel,
        cudaFuncAttributeMaxDynamicSharedMemorySize, BUILD_SMEM);

    // weight repacks (bf16 words)
    repack_w_kernel<<<216, 256>>>(w0, pw0t, C0IN, C0OUT);
    repack_w_kernel<<<1024, 256>>>(w1, pw1t, C0OUT, C1OUT);

    // pad x -> g_xp (bf16 words, channel-last-16)
    pad_x_kernel<<<B4*4*7, 256>>>(x);

    // conv0 + bn + relu : g_xp -> g_y (fp32)
    conv3x3_mma<<<dim3(48, C0OUT/64, B4), 256, CONV_SMEM>>>(
        pxp, pw0t, b0, g0, be0, m0, v0, py, 0, C0IN, C0OUT);

    // branches -> g_tp (bf16 words)
    build_t_kernel<<<B4*24, 1024, BUILD_SMEM>>>();

    // zero q/k sum-of-squares accumulators
    cudaMemsetAsync(psq, 0, B4*384*sizeof(float));

    // conv1 + bn + relu : q/k -> g_qkb bf16 (+g_sq), v -> g_vb bf16
    conv3x3_mma<<<dim3(48, C1OUT/64, B4), 256, CONV_SMEM>>>(
        ptp, pw1t, b1, g1, be1, m1, v1, py /*unused*/, 1, C0OUT, C1OUT);

    // attention logits (bf16 tensor cores; norms folded in epilogue)
    qk_mma_kernel<<<dim3(6, 6, B4), 256>>>(temp);

    // softmax
    softmax_kernel<<<B4*192, 256>>>();

    // attn @ v (bf16 tensor cores)
    av_mma_kernel<<<dim3(72, 6, B4), 256>>>();

    // depthwise conv + bias -> output
    dwconv_kernel<<<dim3(3, 3, B4*192), dim3(16,16)>>>(w2, b2, out);
}

// round 16
// speedup vs baseline: 1.0754x; 1.0754x over previous
#include <cuda_runtime.h>
#include <cuda_bf16.h>
#include <math.h>
#include <stdint.h>

// ---------------- problem constants ----------------
#define B4    4
#define C0IN  64
#define C0OUT 192
#define C1OUT 576
#define NPIX  (96*96)          // 9216
#define PDIM  98
#define PPIX  (98*98)          // 9604
#define HP    48               // pooled size

// ---------------- scratch (device globals; no allocation allowed) ----------
__device__ float g_xp [B4*C0IN*PPIX];     // padded x, [B][4][98][98][8w] bf16x2
__device__ float g_y  [B4*C0OUT*NPIX];    // after conv0+bn+relu (fp32)
__device__ float g_tp [B4*C0OUT*PPIX];    // padded concat, [B][12][98][98][8w] bf16x2
__device__ float g_qkb[B4*384*NPIX/2];    // q/k channels as bf16 [B][384][9216]
__device__ float g_vb [B4*192*NPIX/2];    // v channels as bf16 [B][192][9216]
__device__ float g_att[B4*192*192];       // attention logits / probs
__device__ float g_o  [B4*C0OUT*NPIX];    // attn @ v
__device__ float g_sq [B4*384];           // sum of squares q (0:192) / k (192:384)
__device__ float g_w0t[C0OUT*C0IN*9];     // repacked bf16 weights conv0 (oversized)
__device__ float g_w1t[C1OUT*C0OUT*9];    // repacked bf16 weights conv1 (oversized)

// ---------------- helpers ----------------
__device__ __forceinline__ uint32_t pack_bf16(float lo, float hi) {
    __nv_bfloat162 v = __floats2bfloat162_rn(lo, hi);
    return *(uint32_t*)&v;
}
__device__ __forceinline__ void mma_bf16(float c[4],
    uint32_t a0, uint32_t a1, uint32_t a2, uint32_t a3,
    uint32_t b0, uint32_t b1)
{
    asm volatile(
        "mma.sync.aligned.m16n8k16.row.col.f32.bf16.bf16.f32 "
        "{%0,%1,%2,%3}, {%4,%5,%6,%7}, {%8,%9}, {%0,%1,%2,%3};"
        : "+f"(c[0]), "+f"(c[1]), "+f"(c[2]), "+f"(c[3])
        : "r"(a0), "r"(a1), "r"(a2), "r"(a3), "r"(b0), "r"(b1));
}
__device__ __forceinline__ void cp16(void* s, const void* g) {
    uint32_t sa = (uint32_t)__cvta_generic_to_shared(s);
    asm volatile("cp.async.cg.shared.global [%0], [%1], 16;" :: "r"(sa), "l"(g));
}
// conv word layout (16 ch -> 8 uint32 words): word j holds channel pair pc where
//   j = (pc & 3)*2 + (pc >> 2)  /  pc = (j >> 1) + ((j & 1) << 2)

// =====================================================================
// Weight repack: w[CO,CI,3,3] fp32 -> bf16 words
// =====================================================================
__global__ __launch_bounds__(256) void repack_w_kernel(
    const float* __restrict__ w, float* __restrict__ outf, int CI, int CO)
{
    uint32_t* out = (uint32_t*)outf;
    const int total = CO * (CI >> 4) * 9 * 8;
    for (int d = blockIdx.x*256 + threadIdx.x; d < total; d += gridDim.x*256) {
        int j   = d & 7;
        int rem = d >> 3;
        int co  = rem % CO;  rem /= CO;
        int rs  = rem % 9;
        int chunk = rem / 9;
        int pc = (j >> 1) + ((j & 1) << 2);
        int c_lo = chunk*16 + pc*2;
        out[d] = pack_bf16(w[((size_t)co*CI + c_lo    )*9 + rs],
                           w[((size_t)co*CI + c_lo + 1)*9 + rs]);
    }
}

// =====================================================================
// Implicit-GEMM 3x3 conv + bias + BN + ReLU, bf16 m16n8k16 MMA.
// R12 form: M=64 x 4 rows, 2 CTAs/SM, double-buffered cp.async.
// =====================================================================
#define SW_BYTES 18432   // 9*64*8w*4
#define SX_BYTES 18816   // 6*98*8w*4
#define CONV_SMEM (2*SW_BYTES + 2*SX_BYTES)   // 74496

__global__ __launch_bounds__(256, 2) void conv3x3_mma(
    const float* __restrict__ in,   // bf16 words, [B][CI/16][98][98][8w]
    const float* __restrict__ wt,   // repacked bf16 weights
    const float* __restrict__ bias, const float* __restrict__ gam,
    const float* __restrict__ bet,  const float* __restrict__ mu,
    const float* __restrict__ var,  float* __restrict__ out, // fp32 [B,CO,96,96]
    int do_qk, int CI, int CO)
{
    extern __shared__ uint8_t dynsm[];

    const int tid  = threadIdx.x;
    const int warp = tid >> 5;
    const int lane = tid & 31;
    const int g    = lane >> 2;
    const int tig  = lane & 3;
    const int wm   = warp >> 2;           // 0..1
    const int wn   = warp & 3;            // 0..3

    const int y0o = blockIdx.x * 4;
    const int co0 = blockIdx.y * 64;
    const int b   = blockIdx.z;
    const int nchunks = CI >> 4;

    const uint4* w4 = (const uint4*)wt;

    float acc[2][12][4];
#pragma unroll
    for (int mi = 0; mi < 2; mi++)
#pragma unroll
        for (int ni = 0; ni < 12; ni++)
#pragma unroll
            for (int q = 0; q < 4; q++) acc[mi][ni][q] = 0.f;

    auto load_chunk = [&](int chunk, int stg) {
        uint4* wdst = (uint4*)(dynsm + stg*SW_BYTES);
        const uint4* wsrc = w4 + ((size_t)chunk*9*CO + co0)*2;
        for (int l = tid; l < 1152; l += 256) {
            int rs = l >> 7, t = l & 127;
            cp16(wdst + l, wsrc + (size_t)rs*CO*2 + t);
        }
        uint4* xdst = (uint4*)(dynsm + 2*SW_BYTES + stg*SX_BYTES);
        const uint4* xsrc = (const uint4*)in +
            (((size_t)(b*nchunks + chunk))*PPIX + (size_t)y0o*98)*2;
        for (int l = tid; l < 1176; l += 256)
            cp16(xdst + l, xsrc + l);
    };

    load_chunk(0, 0);
    asm volatile("cp.async.commit_group;" ::: "memory");

    for (int chunk = 0; chunk < nchunks; chunk++) {
        const int st = chunk & 1;
        const bool more = (chunk + 1 < nchunks);
        if (more) {
            load_chunk(chunk + 1, st ^ 1);
            asm volatile("cp.async.commit_group;" ::: "memory");
            asm volatile("cp.async.wait_group 1;" ::: "memory");
        } else {
            asm volatile("cp.async.wait_group 0;" ::: "memory");
        }
        __syncthreads();

        const uint32_t (*W8)[64][8] = (const uint32_t (*)[64][8])(dynsm + st*SW_BYTES);
        const uint32_t (*X8)[98][8] = (const uint32_t (*)[98][8])(dynsm + 2*SW_BYTES + st*SX_BYTES);

#pragma unroll
        for (int r = 0; r < 3; r++) {
#pragma unroll
            for (int s = 0; s < 3; s++) {
                const int rs = r*3 + s;
                const int base0 = wm*32 + g;
                uint2 va00 = *(const uint2*)&W8[rs][base0     ][tig*2];
                uint2 va01 = *(const uint2*)&W8[rs][base0 +  8][tig*2];
                uint2 va10 = *(const uint2*)&W8[rs][base0 + 16][tig*2];
                uint2 va11 = *(const uint2*)&W8[rs][base0 + 24][tig*2];
                const int prow = wn + r;
#pragma unroll
                for (int ni = 0; ni < 12; ni++) {
                    uint2 vb = *(const uint2*)&X8[prow][ni*8 + g + s][tig*2];
                    mma_bf16(acc[0][ni], va00.x, va01.x, va00.y, va01.y, vb.x, vb.y);
                    mma_bf16(acc[1][ni], va10.x, va11.x, va10.y, va11.y, vb.x, vb.y);
                }
            }
        }
        __syncthreads();
    }

    // epilogue
    const int orow = y0o + wn;
#pragma unroll
    for (int mi = 0; mi < 2; mi++) {
        int c_lo = co0 + wm*32 + mi*16 + g;
        int c_hi = c_lo + 8;
        float s_lo  = gam[c_lo] * rsqrtf(var[c_lo] + 1e-5f);
        float sh_lo = (bias[c_lo] - mu[c_lo]) * s_lo + bet[c_lo];
        float s_hi  = gam[c_hi] * rsqrtf(var[c_hi] + 1e-5f);
        float sh_hi = (bias[c_hi] - mu[c_hi]) * s_hi + bet[c_hi];

        if (do_qk && c_lo < 384) {
            uint32_t* qlo = (uint32_t*)g_qkb + (((size_t)(b*384 + c_lo))*NPIX + orow*96)/2;
            uint32_t* qhi = (uint32_t*)g_qkb + (((size_t)(b*384 + c_hi))*NPIX + orow*96)/2;
            float sql = 0.f, sqh = 0.f;
#pragma unroll
            for (int ni = 0; ni < 12; ni++) {
                int x = ni*8 + tig*2;
                float2 v0 = make_float2(fmaxf(acc[mi][ni][0]*s_lo + sh_lo, 0.f),
                                        fmaxf(acc[mi][ni][1]*s_lo + sh_lo, 0.f));
                float2 v1 = make_float2(fmaxf(acc[mi][ni][2]*s_hi + sh_hi, 0.f),
                                        fmaxf(acc[mi][ni][3]*s_hi + sh_hi, 0.f));
                qlo[x/2] = pack_bf16(v0.x, v0.y);
                qhi[x/2] = pack_bf16(v1.x, v1.y);
                sql += v0.x*v0.x + v0.y*v0.y;
                sqh += v1.x*v1.x + v1.y*v1.y;
            }
            sql += __shfl_xor_sync(0xFFFFFFFFu, sql, 1);
            sql += __shfl_xor_sync(0xFFFFFFFFu, sql, 2);
            sqh += __shfl_xor_sync(0xFFFFFFFFu, sqh, 1);
            sqh += __shfl_xor_sync(0xFFFFFFFFu, sqh, 2);
            if (tig == 0) {
                atomicAdd(&g_sq[b*384 + c_lo], sql);
                atomicAdd(&g_sq[b*384 + c_hi], sqh);
            }
        } else if (do_qk) {
            uint32_t* vlo = (uint32_t*)g_vb + (((size_t)(b*192 + c_lo - 384))*NPIX + orow*96)/2;
            uint32_t* vhi = (uint32_t*)g_vb + (((size_t)(b*192 + c_hi - 384))*NPIX + orow*96)/2;
#pragma unroll
            for (int ni = 0; ni < 12; ni++) {
                int x = ni*8 + tig*2;
                vlo[x/2] = pack_bf16(fmaxf(acc[mi][ni][0]*s_lo + sh_lo, 0.f),
                                     fmaxf(acc[mi][ni][1]*s_lo + sh_lo, 0.f));
                vhi[x/2] = pack_bf16(fmaxf(acc[mi][ni][2]*s_hi + sh_hi, 0.f),
                                     fmaxf(acc[mi][ni][3]*s_hi + sh_hi, 0.f));
            }
        } else {
            float* plo = out + (size_t)(b*CO + c_lo)*NPIX + orow*96;
            float* phi = out + (size_t)(b*CO + c_hi)*NPIX + orow*96;
#pragma unroll
            for (int ni = 0; ni < 12; ni++) {
                int x = ni*8 + tig*2;
                *(float2*)(plo + x) = make_float2(fmaxf(acc[mi][ni][0]*s_lo + sh_lo, 0.f),
                                                  fmaxf(acc[mi][ni][1]*s_lo + sh_lo, 0.f));
                *(float2*)(phi + x) = make_float2(fmaxf(acc[mi][ni][2]*s_hi + sh_hi, 0.f),
                                                  fmaxf(acc[mi][ni][3]*s_hi + sh_hi, 0.f));
            }
        }
    }
}

// =====================================================================
// Pad x -> g_xp [B][4][98][98][8w] bf16 words. grid = B4*4*7 row-bands.
// =====================================================================
__global__ __launch_bounds__(256) void pad_x_kernel(const float* __restrict__ x)
{
    const int z = blockIdx.x;
    const int band  = z % 7;
    const int chunk = (z / 7) & 3;
    const int b     = z / 28;
    uint32_t* dp = (uint32_t*)g_xp + ((size_t)(b*4 + chunk))*PPIX*8;
    const float* sp = x + ((size_t)b*C0IN + chunk*16)*NPIX;
    for (int i = threadIdx.x; i < 14*98*8; i += 256) {
        int j = i & 7;
        int p = i >> 3;
        int lrow = p / 98, col = p % 98;
        int row = band*14 + lrow;
        int pc = (j >> 1) + ((j & 1) << 2);
        int c_lo = pc*2;
        float vlo = 0.f, vhi = 0.f;
        if (row >= 1 && row <= 96 && col >= 1 && col <= 96) {
            vlo = sp[(size_t)(c_lo    )*NPIX + (row-1)*96 + (col-1)];
            vhi = sp[(size_t)(c_lo + 1)*NPIX + (row-1)*96 + (col-1)];
        }
        dp[((size_t)row*98 + col)*8 + j] = pack_bf16(vlo, vhi);
    }
}

// =====================================================================
// Branch construction into g_tp [B][12][98][98][8w] bf16 words.
// =====================================================================
#define POOLPAD (HP*HP + 1)
#define BUILD_SMEM (8*POOLPAD*4)    // 73760 B

__global__ __launch_bounds__(1024) void build_t_kernel()
{
    extern __shared__ float pool[];
    const int z = blockIdx.x;         // 0..95
    const int half  = z & 1;
    const int chunk = (z >> 1) % 12;
    const int b     = z / 24;
    const int tid = threadIdx.x;
    uint32_t* dp = (uint32_t*)g_tp + ((size_t)(b*12 + chunk))*PPIX*8;
    const float* yb = g_y + ((size_t)b*192)*NPIX;
    const int c0 = chunk*16 + half*8;

    if (chunk >= 4 && chunk < 8) {        // copy branch
        for (int i = tid; i < PPIX*4; i += 1024) {
            int pl = i & 3;
            int p  = i >> 2;
            int row = p / 98, col = p % 98;
            float vlo = 0.f, vhi = 0.f;
            if (row >= 1 && row <= 96 && col >= 1 && col <= 96) {
                const float* yp = yb + (size_t)(c0 + pl*2)*NPIX + (row-1)*96 + (col-1);
                vlo = yp[0];
                vhi = yp[NPIX];
            }
            dp[(size_t)p*8 + pl*2 + half] = pack_bf16(vlo, vhi);
        }
        return;
    }

    const bool is_max = (chunk < 4);
    for (int i = tid; i < 8*HP*HP; i += 1024) {
        int lc = i / (HP*HP);
        int idx = i % (HP*HP);
        int p = idx / HP, q = idx % HP;
        const float* yp = yb + (size_t)(c0 + lc)*NPIX;
        float a  = yp[(2*p)  *96 + 2*q    ];
        float bb = yp[(2*p)  *96 + 2*q + 1];
        float cc = yp[(2*p+1)*96 + 2*q    ];
        float dd = yp[(2*p+1)*96 + 2*q + 1];
        pool[lc*POOLPAD + idx] = is_max ? fmaxf(fmaxf(a,bb), fmaxf(cc,dd))
                                        : 0.25f*(a + bb + cc + dd);
    }
    __syncthreads();

    for (int i = tid; i < PPIX*4; i += 1024) {
        int pl = i & 3;
        int p  = i >> 2;
        int row = p / 98, col = p % 98;
        uint32_t word = 0;
        if (row >= 1 && row <= 96 && col >= 1 && col <= 96) {
            int h = row - 1, w = col - 1;
            float chf = fminf(fmaxf(0.5f*h - 0.25f, 0.f), 47.f);
            float cwf = fminf(fmaxf(0.5f*w - 0.25f, 0.f), 47.f);
            int hlo = (int)chf; int hhi = min(hlo + 1, 47); float hf = chf - hlo;
            int wlo = (int)cwf; int whi = min(wlo + 1, 47); float wf = cwf - wlo;
            const float* p0 = pool + (pl*2    )*POOLPAD;
            const float* p1 = pool + (pl*2 + 1)*POOLPAD;
            float t0 = p0[hlo*HP + wlo]*(1.f - wf) + p0[hlo*HP + whi]*wf;
            float b0 = p0[hhi*HP + wlo]*(1.f - wf) + p0[hhi*HP + whi]*wf;
            float t1 = p1[hlo*HP + wlo]*(1.f - wf) + p1[hlo*HP + whi]*wf;
            float b1 = p1[hhi*HP + wlo]*(1.f - wf) + p1[hhi*HP + whi]*wf;
            word = pack_bf16(t0*(1.f - hf) + b0*hf, t1*(1.f - hf) + b1*hf);
        }
        dp[(size_t)p*8 + pl*2 + half] = word;
    }
}

// =====================================================================
// QK^T via bf16 MMA, 256-px chunks (36 iters), cp.async double buffer.
// Row stride 528 B (132 words) for conflict-free LDS.64.
// =====================================================================
#define QK_ROWB  528                 // 256 px * 2B + 16 pad
#define QK_HALF  (32*QK_ROWB)        // 16896 B
#define QK_STAGE (2*QK_HALF)         // 33792 B

__global__ __launch_bounds__(256) void qk_mma_kernel(const float* __restrict__ temp)
{
    __shared__ __align__(16) uint8_t smraw[2*QK_STAGE];   // 67584 B
    __shared__ float sQi[32], sKi[32];
    float (*sP)[32][33] = (float(*)[32][33])smraw;        // alias after mainloop

    const int b = blockIdx.z;
    const int i0 = blockIdx.y * 32, j0 = blockIdx.x * 32;
    const int tid  = threadIdx.x;
    const int warp = tid >> 5;
    const int lane = tid & 31;
    const int g    = lane >> 2;
    const int tig  = lane & 3;

    const uint16_t* qkb = (const uint16_t*)g_qkb;
    const uint16_t* Qb = qkb + ((size_t)(b*384) + i0)*NPIX;
    const uint16_t* Kb = qkb + ((size_t)(b*384) + 192 + j0)*NPIX;

    auto load = [&](int kt, int stg) {
        uint8_t* qdst = smraw + stg*QK_STAGE;
        uint8_t* kdst = qdst + QK_HALF;
        for (int l = tid; l < 1024; l += 256) {
            int row = l >> 5, seg = l & 31;
            cp16(qdst + row*QK_ROWB + seg*16, Qb + (size_t)row*NPIX + kt + seg*8);
            cp16(kdst + row*QK_ROWB + seg*16, Kb + (size_t)row*NPIX + kt + seg*8);
        }
    };

    float acc[2][4][4];
#pragma unroll
    for (int mt = 0; mt < 2; mt++)
#pragma unroll
        for (int nt = 0; nt < 4; nt++)
#pragma unroll
            for (int q = 0; q < 4; q++) acc[mt][nt][q] = 0.f;

    load(0, 0);
    asm volatile("cp.async.commit_group;" ::: "memory");

    for (int c = 0; c < 36; c++) {
        const int st = c & 1;
        if (c + 1 < 36) {
            load((c + 1)*256, st ^ 1);
            asm volatile("cp.async.commit_group;" ::: "memory");
            asm volatile("cp.async.wait_group 1;" ::: "memory");
        } else {
            asm volatile("cp.async.wait_group 0;" ::: "memory");
        }
        __syncthreads();

        const uint32_t (*Q8)[132] = (const uint32_t (*)[132])(smraw + st*QK_STAGE);
        const uint32_t (*K8)[132] = (const uint32_t (*)[132])(smraw + st*QK_STAGE + QK_HALF);

#pragma unroll
        for (int ks = 0; ks < 2; ks++) {
            const int kb2 = warp*16 + ks*8;
            uint32_t a[2][4];
#pragma unroll
            for (int mt = 0; mt < 2; mt++) {
                int r0 = mt*16 + g;
                a[mt][0] = Q8[r0    ][kb2 + tig];
                a[mt][1] = Q8[r0 + 8][kb2 + tig];
                a[mt][2] = Q8[r0    ][kb2 + 4 + tig];
                a[mt][3] = Q8[r0 + 8][kb2 + 4 + tig];
            }
#pragma unroll
            for (int nt = 0; nt < 4; nt++) {
                int jr = nt*8 + g;
                uint32_t b0 = K8[jr][kb2 + tig];
                uint32_t b1 = K8[jr][kb2 + 4 + tig];
                mma_bf16(acc[0][nt], a[0][0], a[0][1], a[0][2], a[0][3], b0, b1);
                mma_bf16(acc[1][nt], a[1][0], a[1][1], a[1][2], a[1][3], b0, b1);
            }
        }
        __syncthreads();
    }

    if (tid < 32)
        sQi[tid] = 1.f / fmaxf(sqrtf(g_sq[b*384 + i0 + tid]), 1e-12f);
    else if (tid < 64)
        sKi[tid-32] = 1.f / fmaxf(sqrtf(g_sq[b*384 + 192 + j0 + tid - 32]), 1e-12f);
#pragma unroll
    for (int mt = 0; mt < 2; mt++)
#pragma unroll
        for (int nt = 0; nt < 4; nt++) {
            int r = mt*16 + g, cix = nt*8 + tig*2;
            sP[warp][r    ][cix    ] = acc[mt][nt][0];
            sP[warp][r    ][cix + 1] = acc[mt][nt][1];
            sP[warp][r + 8][cix    ] = acc[mt][nt][2];
            sP[warp][r + 8][cix + 1] = acc[mt][nt][3];
        }
    __syncthreads();

    float tmp = temp[0];
    for (int o = tid; o < 1024; o += 256) {
        int row = o >> 5, col = o & 31;
        float s = 0.f;
#pragma unroll
        for (int w = 0; w < 8; w++) s += sP[w][row][col];
        g_att[(size_t)(b*192 + i0 + row)*192 + j0 + col] =
            s * sQi[row] * tmp * sKi[col];
    }
}

// =====================================================================
// Softmax over last dim (192): one warp per row, shfl-only.
// =====================================================================
__global__ __launch_bounds__(256) void softmax_kernel()
{
    const int row = blockIdx.x*8 + (threadIdx.x >> 5);   // 0..767
    const int lane = threadIdx.x & 31;
    float* p = g_att + (size_t)row * 192;
    float v[6];
#pragma unroll
    for (int k = 0; k < 6; k++) v[k] = p[lane + 32*k];
    float mx = v[0];
#pragma unroll
    for (int k = 1; k < 6; k++) mx = fmaxf(mx, v[k]);
#pragma unroll
    for (int d = 16; d > 0; d >>= 1)
        mx = fmaxf(mx, __shfl_xor_sync(0xFFFFFFFFu, mx, d));
    float s = 0.f;
#pragma unroll
    for (int k = 0; k < 6; k++) { v[k] = __expf(v[k] - mx); s += v[k]; }
#pragma unroll
    for (int d = 16; d > 0; d >>= 1)
        s += __shfl_xor_sync(0xFFFFFFFFu, s, d);
    float inv = 1.f / s;
#pragma unroll
    for (int k = 0; k < 6; k++) p[lane + 32*k] = v[k] * inv;
}

// =====================================================================
// O = A @ V via bf16 MMA (R12 form). CTA tile 32(i) x 128(n).
// =====================================================================
__global__ __launch_bounds__(256) void av_mma_kernel()
{
    __shared__ uint32_t As[32][100];     // 96 words + pad   12.8 KB
    __shared__ uint32_t Vs[128][20];     // 16 words + pad   10.2 KB

    const int b  = blockIdx.z;
    const int i0 = blockIdx.y * 32;
    const int n0 = blockIdx.x * 128;
    const int tid  = threadIdx.x;
    const int warp = tid >> 5;
    const int lane = tid & 31;
    const int g    = lane >> 2;
    const int tig  = lane & 3;

    const float* A = g_att + (size_t)b * 192 * 192;
    const uint32_t* vb = (const uint32_t*)g_vb + (size_t)b * 192 * (NPIX/2);

#pragma unroll
    for (int jj = 0; jj < 12; jj++) {
        int l = jj*256 + tid;
        int r = l / 96, w = l % 96;
        float2 a2 = *(const float2*)&A[(size_t)(i0 + r)*192 + 2*w];
        As[r][w] = pack_bf16(a2.x, a2.y);
    }

    float acc[2][2][4];
#pragma unroll
    for (int mt = 0; mt < 2; mt++)
#pragma unroll
        for (int nt = 0; nt < 2; nt++)
#pragma unroll
            for (int q = 0; q < 4; q++) acc[mt][nt][q] = 0.f;

    for (int kt = 0; kt < 192; kt += 32) {
        __syncthreads();
        for (int l = tid; l < 1024; l += 256) {
            int pp = l & 63;
            int w  = l >> 6;
            uint32_t u0 = vb[(size_t)(kt + 2*w    )*(NPIX/2) + (n0 >> 1) + pp];
            uint32_t u1 = vb[(size_t)(kt + 2*w + 1)*(NPIX/2) + (n0 >> 1) + pp];
            Vs[2*pp    ][w] = __byte_perm(u0, u1, 0x5410);
            Vs[2*pp + 1][w] = __byte_perm(u0, u1, 0x7632);
        }
        __syncthreads();

        const int wt0 = kt >> 1;
#pragma unroll
        for (int ks = 0; ks < 2; ks++) {
            const int kw = wt0 + ks*8;
            uint32_t a[2][4];
#pragma unroll
            for (int mt = 0; mt < 2; mt++) {
                int r0 = mt*16 + g;
                a[mt][0] = As[r0    ][kw + tig];
                a[mt][1] = As[r0 + 8][kw + tig];
                a[mt][2] = As[r0    ][kw + 4 + tig];
                a[mt][3] = As[r0 + 8][kw + 4 + tig];
            }
#pragma unroll
            for (int nt = 0; nt < 2; nt++) {
                int nr = warp*16 + nt*8 + g;
                uint32_t b0 = Vs[nr][ks*8 + tig];
                uint32_t b1 = Vs[nr][ks*8 + 4 + tig];
                mma_bf16(acc[0][nt], a[0][0], a[0][1], a[0][2], a[0][3], b0, b1);
                mma_bf16(acc[1][nt], a[1][0], a[1][1], a[1][2], a[1][3], b0, b1);
            }
        }
    }

#pragma unroll
    for (int mt = 0; mt < 2; mt++) {
        int r = i0 + mt*16 + g;
#pragma unroll
        for (int nt = 0; nt < 2; nt++) {
            int nc = n0 + warp*16 + nt*8 + tig*2;
            *(float2*)&g_o[((size_t)(b*192) + r    )*NPIX + nc] =
                make_float2(acc[mt][nt][0], acc[mt][nt][1]);
            *(float2*)&g_o[((size_t)(b*192) + r + 8)*NPIX + nc] =
                make_float2(acc[mt][nt][2], acc[mt][nt][3]);
        }
    }
}

// =====================================================================
// Depthwise 3x3 conv (pad 1) + bias on g_o -> d_out.
// =====================================================================
__global__ __launch_bounds__(256) void dwconv_kernel(
    const float* __restrict__ w2, const float* __restrict__ b2,
    float* __restrict__ out)
{
    __shared__ float sIn[34][34];
    const int tx = threadIdx.x, ty = threadIdx.y;
    const int tid = ty*16 + tx;
    const int z = blockIdx.z;            // 0..767
    const int b = z / 192, c = z % 192;
    const int y0 = blockIdx.y*32, x0 = blockIdx.x*32;
    const float* ip = g_o + (size_t)(b*192 + c) * NPIX;

    for (int l = tid; l < 34*34; l += 256) {
        int i = l / 34, j = l % 34;
        int gy = y0 - 1 + i, gx = x0 - 1 + j;
        float v = 0.f;
        if ((unsigned)gy < 96u && (unsigned)gx < 96u) v = ip[gy*96 + gx];
        ((float*)sIn)[l] = v;
    }
    __syncthreads();

    float wv[9];
#pragma unroll
    for (int k = 0; k < 9; k++) wv[k] = w2[c*9 + k];
    float bb = b2[c];

    float iv[4][4];
#pragma unroll
    for (int r = 0; r < 4; r++)
#pragma unroll
        for (int cc = 0; cc < 4; cc++) iv[r][cc] = sIn[2*ty + r][2*tx + cc];

    float a00 = bb, a01 = bb, a10 = bb, a11 = bb;
#pragma unroll
    for (int ky = 0; ky < 3; ky++)
#pragma unroll
        for (int kx = 0; kx < 3; kx++) {
            float wk = wv[ky*3 + kx];
            a00 += iv[ky  ][kx  ]*wk;
            a01 += iv[ky  ][kx+1]*wk;
            a10 += iv[ky+1][kx  ]*wk;
            a11 += iv[ky+1][kx+1]*wk;
        }
    const int oy = y0 + 2*ty, ox = x0 + 2*tx;
    float* op = out + (size_t)(b*192 + c)*NPIX + oy*96 + ox;
    op[0] = a00; op[1] = a01; op[96] = a10; op[97] = a11;
}

// =====================================================================
// Launcher
// =====================================================================
extern "C" void kernel_launch(void* const* d_in, const int* in_sizes, int n_in,
                              void* d_out, int out_size)
{
    const float* x    = (const float*)d_in[0];
    const float* w0   = (const float*)d_in[1];
    const float* b0   = (const float*)d_in[2];
    const float* g0   = (const float*)d_in[3];
    const float* be0  = (const float*)d_in[4];
    const float* m0   = (const float*)d_in[5];
    const float* v0   = (const float*)d_in[6];
    const float* w1   = (const float*)d_in[7];
    const float* b1   = (const float*)d_in[8];
    const float* g1   = (const float*)d_in[9];
    const float* be1  = (const float*)d_in[10];
    const float* m1   = (const float*)d_in[11];
    const float* v1   = (const float*)d_in[12];
    const float* temp = (const float*)d_in[13];
    const float* w2   = (const float*)d_in[14];
    const float* b2   = (const float*)d_in[15];
    float* out = (float*)d_out;

    float *pxp, *py, *ptp, *pw0t, *pw1t, *psq;
    cudaGetSymbolAddress((void**)&pxp,  g_xp);
    cudaGetSymbolAddress((void**)&py,   g_y);
    cudaGetSymbolAddress((void**)&ptp,  g_tp);
    cudaGetSymbolAddress((void**)&pw0t, g_w0t);
    cudaGetSymbolAddress((void**)&pw1t, g_w1t);
    cudaGetSymbolAddress((void**)&psq,  g_sq);

    cudaFuncSetAttribute(conv3x3_mma,
        cudaFuncAttributeMaxDynamicSharedMemorySize, CONV_SMEM);
    cudaFuncSetAttribute(build_t_kernel,
        cudaFuncAttributeMaxDynamicSharedMemorySize, BUILD_SMEM);

    // weight repacks (bf16 words)
    repack_w_kernel<<<216, 256>>>(w0, pw0t, C0IN, C0OUT);
    repack_w_kernel<<<1024, 256>>>(w1, pw1t, C0OUT, C1OUT);

    // pad x -> g_xp (bf16 words, channel-last-16)
    pad_x_kernel<<<B4*4*7, 256>>>(x);

    // conv0 + bn + relu : g_xp -> g_y (fp32)
    conv3x3_mma<<<dim3(24, C0OUT/64, B4), 256, CONV_SMEM>>>(
        pxp, pw0t, b0, g0, be0, m0, v0, py, 0, C0IN, C0OUT);

    // branches -> g_tp (bf16 words)
    build_t_kernel<<<B4*24, 1024, BUILD_SMEM>>>();

    // zero q/k sum-of-squares accumulators
    cudaMemsetAsync(psq, 0, B4*384*sizeof(float));

    // conv1 + bn + relu : q/k -> g_qkb bf16 (+g_sq), v -> g_vb bf16
    conv3x3_mma<<<dim3(24, C1OUT/64, B4), 256, CONV_SMEM>>>(
        ptp, pw1t, b1, g1, be1, m1, v1, py /*unused*/, 1, C0OUT, C1OUT);

    // attention logits (bf16 tensor cores; norms folded in epilogue)
    qk_mma_kernel<<<dim3(6, 6, B4), 256>>>(temp);

    // softmax (warp per row)
    softmax_kernel<<<96, 256>>>();

    // attn @ v (bf16 tensor cores)
    av_mma_kernel<<<dim3(72, 6, B4), 256>>>();

    // depthwise conv + bias -> output
    dwconv_kernel<<<dim3(3, 3, B4*192), dim3(16,16)>>>(w2, b2, out);
}